// round 1
// baseline (speedup 1.0000x reference)
#include <cuda_runtime.h>
#include <cstdint>
#include <cstdio>

// Problem constants
namespace {
constexpr int Bb = 4, Tt = 4096, Cc = 2048, Hh = 16, DhD = 128;
constexpr int Mrows = Bb * Tt;            // 16384
constexpr int NCHUNK = 64;                // scan chunks
constexpr int LCH = Tt / NCHUNK;          // 64 steps per chunk
}

// ---------------- scratch (static device globals; no allocation allowed) ---
__device__ float g_xconv[(size_t)Bb * Tt * Cc];
__device__ float g_q   [(size_t)Bb * Tt * Cc];
__device__ float g_k   [(size_t)Bb * Tt * Cc];
__device__ float g_v   [(size_t)Bb * Tt * Cc];
__device__ float g_gate[(size_t)Bb * Tt * Cc];
__device__ float g_att [(size_t)Bb * Tt * Cc];
__device__ float g_y   [(size_t)Bb * Tt * Cc];
__device__ float g_F    [(size_t)Bb * Hh * NCHUNK * DhD];
__device__ float g_carry[(size_t)Bb * Hh * NCHUNK * DhD];

// ---------------- helpers --------------------------------------------------
__device__ __forceinline__ uint32_t f2tf32(float f) {
    uint32_t u;
    asm("cvt.rna.tf32.f32 %0, %1;" : "=r"(u) : "f"(f));
    return u;
}

__device__ __forceinline__ void mma_tf32(float& d0, float& d1, float& d2, float& d3,
                                         uint32_t a0, uint32_t a1, uint32_t a2, uint32_t a3,
                                         uint32_t b0, uint32_t b1) {
    asm volatile(
        "mma.sync.aligned.m16n8k8.row.col.f32.tf32.tf32.f32 "
        "{%0,%1,%2,%3}, {%4,%5,%6,%7}, {%8,%9}, {%0,%1,%2,%3};\n"
        : "+f"(d0), "+f"(d1), "+f"(d2), "+f"(d3)
        : "r"(a0), "r"(a1), "r"(a2), "r"(a3), "r"(b0), "r"(b1));
}

// ---------------- 1) causal depthwise conv (K=4) + SiLU --------------------
__global__ void conv_silu_kernel(const float* __restrict__ x,
                                 const float* __restrict__ w,
                                 const float* __restrict__ bias) {
    int idx = blockIdx.x * blockDim.x + threadIdx.x;   // over B*T*C
    int c  = idx & (Cc - 1);
    int bt = idx >> 11;                                 // /2048
    int t  = bt & (Tt - 1);
    float acc = bias[c];
    const float* wr = w + c * 4;
    int base = (bt - t) * Cc + c;                       // b*T*C + c
    #pragma unroll
    for (int j = 0; j < 4; j++) {
        int tt = t - 3 + j;
        if (tt >= 0) acc = fmaf(x[base + tt * Cc], wr[j], acc);
    }
    g_xconv[idx] = acc / (1.0f + expf(-acc));           // SiLU
}

// ---------------- 2) TF32 tensor-core GEMM: Out = A[M,K] * W[N,K]^T --------
// mode 0: plain.  mode 1: sigmoid(out + bias[col]).
__global__ __launch_bounds__(256)
void gemm_tf32_kernel(const float* __restrict__ A, const float* __restrict__ W,
                      float* __restrict__ Out, int M, int N, int K,
                      const float* __restrict__ bias, int mode) {
    constexpr int BM = 128, BN = 128, BKk = 16, PAD = 20;
    __shared__ uint32_t As[BM * PAD];
    __shared__ uint32_t Bs[BN * PAD];

    const int tid  = threadIdx.x;
    const int warp = tid >> 5, lane = tid & 31;
    const int gid  = lane >> 2, tg = lane & 3;
    const int wm   = warp & 1;       // 0..1  -> 64-row slab
    const int wn   = warp >> 1;      // 0..3  -> 32-col slab
    const int bm   = blockIdx.y * BM;
    const int bn   = blockIdx.x * BN;

    float acc[4][4][4];
    #pragma unroll
    for (int i = 0; i < 4; i++)
        #pragma unroll
        for (int j = 0; j < 4; j++)
            #pragma unroll
            for (int l = 0; l < 4; l++) acc[i][j][l] = 0.0f;

    const int lrow = tid >> 2;          // 0..63
    const int lcol = (tid & 3) * 4;     // 0,4,8,12

    for (int k0 = 0; k0 < K; k0 += BKk) {
        #pragma unroll
        for (int r = 0; r < 2; r++) {
            int row = lrow + r * 64;
            float4 av = *reinterpret_cast<const float4*>(
                &A[(size_t)(bm + row) * K + k0 + lcol]);
            uint4 ua = make_uint4(f2tf32(av.x), f2tf32(av.y), f2tf32(av.z), f2tf32(av.w));
            *reinterpret_cast<uint4*>(&As[row * PAD + lcol]) = ua;
            float4 bv = *reinterpret_cast<const float4*>(
                &W[(size_t)(bn + row) * K + k0 + lcol]);
            uint4 ub = make_uint4(f2tf32(bv.x), f2tf32(bv.y), f2tf32(bv.z), f2tf32(bv.w));
            *reinterpret_cast<uint4*>(&Bs[row * PAD + lcol]) = ub;
        }
        __syncthreads();

        #pragma unroll
        for (int kk = 0; kk < BKk; kk += 8) {
            uint32_t af[4][4], bf[4][2];
            #pragma unroll
            for (int mt = 0; mt < 4; mt++) {
                int rb = wm * 64 + mt * 16;
                af[mt][0] = As[(rb + gid    ) * PAD + kk + tg];
                af[mt][1] = As[(rb + gid + 8) * PAD + kk + tg];
                af[mt][2] = As[(rb + gid    ) * PAD + kk + tg + 4];
                af[mt][3] = As[(rb + gid + 8) * PAD + kk + tg + 4];
            }
            #pragma unroll
            for (int nt = 0; nt < 4; nt++) {
                int cb = wn * 32 + nt * 8;
                bf[nt][0] = Bs[(cb + gid) * PAD + kk + tg];
                bf[nt][1] = Bs[(cb + gid) * PAD + kk + tg + 4];
            }
            #pragma unroll
            for (int mt = 0; mt < 4; mt++)
                #pragma unroll
                for (int nt = 0; nt < 4; nt++)
                    mma_tf32(acc[mt][nt][0], acc[mt][nt][1], acc[mt][nt][2], acc[mt][nt][3],
                             af[mt][0], af[mt][1], af[mt][2], af[mt][3],
                             bf[nt][0], bf[nt][1]);
        }
        __syncthreads();
    }

    // epilogue
    #pragma unroll
    for (int mt = 0; mt < 4; mt++) {
        #pragma unroll
        for (int nt = 0; nt < 4; nt++) {
            int row = bm + wm * 64 + mt * 16 + gid;
            int col = bn + wn * 32 + nt * 8 + tg * 2;
            float v0 = acc[mt][nt][0], v1 = acc[mt][nt][1];
            float v2 = acc[mt][nt][2], v3 = acc[mt][nt][3];
            if (mode == 1) {
                float b0 = bias[col], b1 = bias[col + 1];
                v0 = 1.0f / (1.0f + expf(-(v0 + b0)));
                v1 = 1.0f / (1.0f + expf(-(v1 + b1)));
                v2 = 1.0f / (1.0f + expf(-(v2 + b0)));
                v3 = 1.0f / (1.0f + expf(-(v3 + b1)));
            }
            *reinterpret_cast<float2*>(&Out[(size_t)row * N + col])       = make_float2(v0, v1);
            *reinterpret_cast<float2*>(&Out[(size_t)(row + 8) * N + col]) = make_float2(v2, v3);
        }
    }
}

// ---------------- 3) L2-normalize q and k over Dh=128 ----------------------
__global__ void l2norm_kernel(float* __restrict__ q, float* __restrict__ k) {
    int gw   = (blockIdx.x * blockDim.x + threadIdx.x) >> 5;  // row of 128
    int lane = threadIdx.x & 31;
    if (gw >= Bb * Tt * Hh) return;
    size_t base = (size_t)gw * DhD + lane * 4;

    float4 qv = *reinterpret_cast<const float4*>(q + base);
    float ss = qv.x * qv.x + qv.y * qv.y + qv.z * qv.z + qv.w * qv.w;
    #pragma unroll
    for (int o = 16; o; o >>= 1) ss += __shfl_xor_sync(0xffffffffu, ss, o);
    float inv = 1.0f / fmaxf(sqrtf(ss), 1e-12f);
    qv.x *= inv; qv.y *= inv; qv.z *= inv; qv.w *= inv;
    *reinterpret_cast<float4*>(q + base) = qv;

    float4 kv = *reinterpret_cast<const float4*>(k + base);
    float sk = kv.x * kv.x + kv.y * kv.y + kv.z * kv.z + kv.w * kv.w;
    #pragma unroll
    for (int o = 16; o; o >>= 1) sk += __shfl_xor_sync(0xffffffffu, sk, o);
    float invk = 1.0f / fmaxf(sqrtf(sk), 1e-12f);
    kv.x *= invk; kv.y *= invk; kv.z *= invk; kv.w *= invk;
    *reinterpret_cast<float4*>(k + base) = kv;
}

// ---------------- 4) chunked decayed scan ----------------------------------
// pass1: per-chunk local scan final (zero init)
__global__ void scan_pass1(const float* __restrict__ k, const float* __restrict__ v,
                           const float* __restrict__ gamma) {
    int blk = blockIdx.x;
    int c  = blk % NCHUNK;
    int bh = blk / NCHUNK;
    int h  = bh % Hh;
    int b  = bh / Hh;
    int d  = threadIdx.x;
    float g = gamma[h];
    size_t idx = ((size_t)(b * Tt + c * LCH)) * Cc + h * DhD + d;
    float S = 0.0f;
    #pragma unroll 4
    for (int i = 0; i < LCH; i++) {
        S = fmaf(g, S, k[idx] * v[idx]);
        idx += Cc;
    }
    g_F[((size_t)bh * NCHUNK + c) * DhD + d] = S;
}

// pass2: sequential carry combine across chunks (exact: linear recurrence)
__global__ void scan_pass2(const float* __restrict__ gamma) {
    int tid = blockIdx.x * blockDim.x + threadIdx.x;
    if (tid >= Bb * Hh * DhD) return;
    int d  = tid & (DhD - 1);
    int bh = tid >> 7;
    int h  = bh % Hh;
    float g  = gamma[h];
    float gL = powf(g, (float)LCH);     // exact 1.0 for gamma=1 head
    float carry = 0.0f;
    for (int c = 0; c < NCHUNK; c++) {
        size_t o = ((size_t)bh * NCHUNK + c) * DhD + d;
        g_carry[o] = carry;
        carry = fmaf(gL, carry, g_F[o]);
    }
}

// pass3: replay with carry, write gated output out = gate * S * q
__global__ void scan_pass3(const float* __restrict__ k, const float* __restrict__ v,
                           const float* __restrict__ q, const float* __restrict__ gate,
                           const float* __restrict__ gamma) {
    int blk = blockIdx.x;
    int c  = blk % NCHUNK;
    int bh = blk / NCHUNK;
    int h  = bh % Hh;
    int b  = bh / Hh;
    int d  = threadIdx.x;
    float g = gamma[h];
    float S = g_carry[((size_t)bh * NCHUNK + c) * DhD + d];
    size_t idx = ((size_t)(b * Tt + c * LCH)) * Cc + h * DhD + d;
    #pragma unroll 4
    for (int i = 0; i < LCH; i++) {
        S = fmaf(g, S, k[idx] * v[idx]);
        g_att[idx] = gate[idx] * S * q[idx];
        idx += Cc;
    }
}

// ---------------- 5) LayerNorm over C=2048 ---------------------------------
__global__ __launch_bounds__(256)
void ln_kernel(const float* __restrict__ y, const float* __restrict__ lw,
               const float* __restrict__ lb, float* __restrict__ out) {
    int row = blockIdx.x;
    int tid = threadIdx.x;
    const float4* yr = reinterpret_cast<const float4*>(y + (size_t)row * Cc);
    float4* orow     = reinterpret_cast<float4*>(out + (size_t)row * Cc);

    float4 v0 = yr[tid];
    float4 v1 = yr[tid + 256];
    float sum = v0.x + v0.y + v0.z + v0.w + v1.x + v1.y + v1.z + v1.w;
    float sq  = v0.x * v0.x + v0.y * v0.y + v0.z * v0.z + v0.w * v0.w
              + v1.x * v1.x + v1.y * v1.y + v1.z * v1.z + v1.w * v1.w;

    #pragma unroll
    for (int o = 16; o; o >>= 1) {
        sum += __shfl_xor_sync(0xffffffffu, sum, o);
        sq  += __shfl_xor_sync(0xffffffffu, sq, o);
    }
    __shared__ float ssum[8], ssq[8];
    __shared__ float s_mu, s_inv;
    int warp = tid >> 5, lane = tid & 31;
    if (lane == 0) { ssum[warp] = sum; ssq[warp] = sq; }
    __syncthreads();
    if (tid == 0) {
        float ts = 0.0f, tq = 0.0f;
        #pragma unroll
        for (int i = 0; i < 8; i++) { ts += ssum[i]; tq += ssq[i]; }
        float mu  = ts / (float)Cc;
        float var = tq / (float)Cc - mu * mu;
        s_mu  = mu;
        s_inv = rsqrtf(var + 1e-5f);
    }
    __syncthreads();
    float mu = s_mu, inv = s_inv;

    const float4 w0 = reinterpret_cast<const float4*>(lw)[tid];
    const float4 w1 = reinterpret_cast<const float4*>(lw)[tid + 256];
    const float4 b0 = reinterpret_cast<const float4*>(lb)[tid];
    const float4 b1 = reinterpret_cast<const float4*>(lb)[tid + 256];

    float4 o0, o1;
    o0.x = (v0.x - mu) * inv * w0.x + b0.x;
    o0.y = (v0.y - mu) * inv * w0.y + b0.y;
    o0.z = (v0.z - mu) * inv * w0.z + b0.z;
    o0.w = (v0.w - mu) * inv * w0.w + b0.w;
    o1.x = (v1.x - mu) * inv * w1.x + b1.x;
    o1.y = (v1.y - mu) * inv * w1.y + b1.y;
    o1.z = (v1.z - mu) * inv * w1.z + b1.z;
    o1.w = (v1.w - mu) * inv * w1.w + b1.w;
    orow[tid]       = o0;
    orow[tid + 256] = o1;
}

// ---------------- host orchestration ---------------------------------------
extern "C" void kernel_launch(void* const* d_in, const int* in_sizes, int n_in,
                              void* d_out, int out_size) {
    (void)in_sizes; (void)n_in; (void)out_size;
    const float* x      = (const float*)d_in[0];
    const float* Wq     = (const float*)d_in[1];
    const float* Wk     = (const float*)d_in[2];
    const float* Wv     = (const float*)d_in[3];
    const float* Wo     = (const float*)d_in[4];
    const float* conv_w = (const float*)d_in[5];
    const float* conv_b = (const float*)d_in[6];
    const float* gate_w = (const float*)d_in[7];
    const float* gate_b = (const float*)d_in[8];
    const float* ln_w   = (const float*)d_in[9];
    const float* ln_b   = (const float*)d_in[10];
    const float* gamma  = (const float*)d_in[11];

    float *p_xconv, *p_q, *p_k, *p_v, *p_gate, *p_att, *p_y;
    cudaGetSymbolAddress((void**)&p_xconv, g_xconv);
    cudaGetSymbolAddress((void**)&p_q, g_q);
    cudaGetSymbolAddress((void**)&p_k, g_k);
    cudaGetSymbolAddress((void**)&p_v, g_v);
    cudaGetSymbolAddress((void**)&p_gate, g_gate);
    cudaGetSymbolAddress((void**)&p_att, g_att);
    cudaGetSymbolAddress((void**)&p_y, g_y);

    // 1) depthwise conv + SiLU
    conv_silu_kernel<<<(Mrows * Cc) / 256, 256>>>(x, conv_w, conv_b);

    // 2) projections (TF32 tensor cores)
    dim3 ggrid(Cc / 128, Mrows / 128);   // (16, 128)
    gemm_tf32_kernel<<<ggrid, 256>>>(x,       Wq,     p_q,    Mrows, Cc, Cc, nullptr, 0);
    gemm_tf32_kernel<<<ggrid, 256>>>(x,       Wk,     p_k,    Mrows, Cc, Cc, nullptr, 0);
    gemm_tf32_kernel<<<ggrid, 256>>>(x,       Wv,     p_v,    Mrows, Cc, Cc, nullptr, 0);
    gemm_tf32_kernel<<<ggrid, 256>>>(p_xconv, gate_w, p_gate, Mrows, Cc, Cc, gate_b, 1);

    // 3) l2norm q, k
    l2norm_kernel<<<(Bb * Tt * Hh) / 8, 256>>>(p_q, p_k);

    // 4) decayed scan (chunked, exact)
    scan_pass1<<<Bb * Hh * NCHUNK, DhD>>>(p_k, p_v, gamma);
    scan_pass2<<<(Bb * Hh * DhD + 127) / 128, 128>>>(gamma);
    scan_pass3<<<Bb * Hh * NCHUNK, DhD>>>(p_k, p_v, p_q, p_gate, gamma);

    // 5) output projection + LayerNorm
    gemm_tf32_kernel<<<ggrid, 256>>>(p_att, Wo, p_y, Mrows, Cc, Cc, nullptr, 0);
    ln_kernel<<<Mrows, 256>>>(p_y, ln_w, ln_b, (float*)d_out);
}

// round 2
// speedup vs baseline: 1.2969x; 1.2969x over previous
#include <cuda_runtime.h>
#include <cstdint>
#include <cstdio>

// Problem constants
namespace {
constexpr int Bb = 4, Tt = 4096, Cc = 2048, Hh = 16, DhD = 128;
constexpr int Mrows = Bb * Tt;            // 16384
constexpr int NCHUNK = 64;                // scan chunks
constexpr int LCH = Tt / NCHUNK;          // 64 steps per chunk
}

// ---------------- scratch (static device globals; no allocation allowed) ---
__device__ float g_xconv[(size_t)Bb * Tt * Cc];
__device__ float g_q   [(size_t)Bb * Tt * Cc];
__device__ float g_k   [(size_t)Bb * Tt * Cc];
__device__ float g_v   [(size_t)Bb * Tt * Cc];
__device__ float g_gate[(size_t)Bb * Tt * Cc];
__device__ float g_att [(size_t)Bb * Tt * Cc];
__device__ float g_y   [(size_t)Bb * Tt * Cc];
__device__ float g_xt  [(size_t)Bb * Tt * Cc];      // tf32-rounded x
__device__ float g_Wqt [(size_t)Cc * Cc];
__device__ float g_Wkt [(size_t)Cc * Cc];
__device__ float g_Wvt [(size_t)Cc * Cc];
__device__ float g_Wot [(size_t)Cc * Cc];
__device__ float g_Wgt [(size_t)Cc * Cc];
__device__ float g_F    [(size_t)Bb * Hh * NCHUNK * DhD];
__device__ float g_carry[(size_t)Bb * Hh * NCHUNK * DhD];

// ---------------- helpers --------------------------------------------------
__device__ __forceinline__ uint32_t f2tf32(float f) {
    uint32_t u;
    asm("cvt.rna.tf32.f32 %0, %1;" : "=r"(u) : "f"(f));
    return u;
}

__device__ __forceinline__ float tf32r(float f) {
    return __uint_as_float(f2tf32(f));
}

__device__ __forceinline__ void mma_tf32(float& d0, float& d1, float& d2, float& d3,
                                         uint32_t a0, uint32_t a1, uint32_t a2, uint32_t a3,
                                         uint32_t b0, uint32_t b1) {
    asm volatile(
        "mma.sync.aligned.m16n8k8.row.col.f32.tf32.tf32.f32 "
        "{%0,%1,%2,%3}, {%4,%5,%6,%7}, {%8,%9}, {%0,%1,%2,%3};\n"
        : "+f"(d0), "+f"(d1), "+f"(d2), "+f"(d3)
        : "r"(a0), "r"(a1), "r"(a2), "r"(a3), "r"(b0), "r"(b1));
}

// ---------------- 0) tf32 pre-round (vectorized) ----------------------------
__global__ void cvt_tf32_kernel(const float* __restrict__ in, float* __restrict__ out) {
    int i = blockIdx.x * blockDim.x + threadIdx.x;
    float4 v = reinterpret_cast<const float4*>(in)[i];
    v.x = tf32r(v.x); v.y = tf32r(v.y); v.z = tf32r(v.z); v.w = tf32r(v.w);
    reinterpret_cast<float4*>(out)[i] = v;
}

// ---------------- 1) causal depthwise conv (K=4) + SiLU (tf32-rounded out) --
__global__ void conv_silu_kernel(const float* __restrict__ x,
                                 const float* __restrict__ w,
                                 const float* __restrict__ bias) {
    int idx = blockIdx.x * blockDim.x + threadIdx.x;   // over B*T*C
    int c  = idx & (Cc - 1);
    int bt = idx >> 11;                                 // /2048
    int t  = bt & (Tt - 1);
    float acc = bias[c];
    const float* wr = w + c * 4;
    int base = (bt - t) * Cc + c;                       // b*T*C + c
    #pragma unroll
    for (int j = 0; j < 4; j++) {
        int tt = t - 3 + j;
        if (tt >= 0) acc = fmaf(x[base + tt * Cc], wr[j], acc);
    }
    float s = acc / (1.0f + expf(-acc));                // SiLU
    g_xconv[idx] = tf32r(s);                            // pre-round for GEMM
}

// ---------------- 2) TF32 tensor-core GEMM, cp.async 3-stage pipeline ------
// Out = A[M,K] * W[N,K]^T.  A, W must be pre-rounded to tf32.
// mode 0: plain.  mode 1: sigmoid(out + bias[col]).
// smem layout per (matrix,stage): 128 rows x 16 words, XOR-swizzled chunks:
//   word(row,k) at row*16 + (((k>>2) ^ ((row>>1)&3))<<2) + (k&3)
__global__ __launch_bounds__(256)
void gemm_tf32_pipe(const float* __restrict__ A, const float* __restrict__ W,
                    float* __restrict__ Out, int M, int N, int K,
                    const float* __restrict__ bias, int mode) {
    constexpr int BM = 128, BN = 128, BKk = 16, ST = 3;
    __shared__ uint32_t As[ST][BM * BKk];
    __shared__ uint32_t Bs[ST][BN * BKk];

    const int tid  = threadIdx.x;
    const int warp = tid >> 5, lane = tid & 31;
    const int gid  = lane >> 2, tg = lane & 3;
    const int wm   = warp & 1;       // 0..1  -> 64-row slab
    const int wn   = warp >> 1;      // 0..3  -> 32-col slab
    const int bm   = blockIdx.y * BM;
    const int bn   = blockIdx.x * BN;

    const int lr = tid >> 2;         // 0..63  (loader row)
    const int lc = tid & 3;          // chunk 0..3

    uint32_t sA = (uint32_t)__cvta_generic_to_shared(&As[0][0]);
    uint32_t sB = (uint32_t)__cvta_generic_to_shared(&Bs[0][0]);

    auto issue = [&](int s, int k0) {
        #pragma unroll
        for (int r = 0; r < 2; r++) {
            int row = lr + r * 64;
            int sw  = (row >> 1) & 3;
            uint32_t off = (uint32_t)(s * BM * BKk + row * 16 + ((lc ^ sw) << 2)) * 4u;
            const float* gA = A + (size_t)(bm + row) * K + k0 + lc * 4;
            asm volatile("cp.async.cg.shared.global [%0], [%1], 16;\n"
                         :: "r"(sA + off), "l"(gA));
            const float* gB = W + (size_t)(bn + row) * K + k0 + lc * 4;
            asm volatile("cp.async.cg.shared.global [%0], [%1], 16;\n"
                         :: "r"(sB + off), "l"(gB));
        }
        asm volatile("cp.async.commit_group;\n");
    };

    float acc[4][4][4] = {};

    issue(0, 0);
    issue(1, BKk);

    int s = 0;
    for (int k0 = 0; k0 < K; k0 += BKk) {
        asm volatile("cp.async.wait_group 1;\n" ::: "memory");
        __syncthreads();

        int kn = k0 + 2 * BKk;
        if (kn < K) {
            int s2 = s + 2; if (s2 >= ST) s2 -= ST;
            issue(s2, kn);
        }

        const uint32_t* Ab = &As[s][0];
        const uint32_t* Bb = &Bs[s][0];
        #pragma unroll
        for (int kk = 0; kk < BKk; kk += 8) {
            const int c0 = kk >> 2;
            uint32_t af[4][4], bf[4][2];
            #pragma unroll
            for (int mt = 0; mt < 4; mt++) {
                int row = wm * 64 + mt * 16 + gid;        // row&15 == gid
                int sw  = (row >> 1) & 3;
                int b0i = row * 16 + tg;
                int b1i = (row + 8) * 16 + tg;
                af[mt][0] = Ab[b0i + ((c0 ^ sw) << 2)];
                af[mt][1] = Ab[b1i + ((c0 ^ sw) << 2)];
                af[mt][2] = Ab[b0i + (((c0 + 1) ^ sw) << 2)];
                af[mt][3] = Ab[b1i + (((c0 + 1) ^ sw) << 2)];
            }
            #pragma unroll
            for (int nt = 0; nt < 4; nt++) {
                int col = wn * 32 + nt * 8 + gid;
                int sw  = (col >> 1) & 3;
                int bi  = col * 16 + tg;
                bf[nt][0] = Bb[bi + ((c0 ^ sw) << 2)];
                bf[nt][1] = Bb[bi + (((c0 + 1) ^ sw) << 2)];
            }
            #pragma unroll
            for (int mt = 0; mt < 4; mt++)
                #pragma unroll
                for (int nt = 0; nt < 4; nt++)
                    mma_tf32(acc[mt][nt][0], acc[mt][nt][1], acc[mt][nt][2], acc[mt][nt][3],
                             af[mt][0], af[mt][1], af[mt][2], af[mt][3],
                             bf[nt][0], bf[nt][1]);
        }
        s++; if (s >= ST) s = 0;
    }

    // epilogue
    #pragma unroll
    for (int mt = 0; mt < 4; mt++) {
        #pragma unroll
        for (int nt = 0; nt < 4; nt++) {
            int row = bm + wm * 64 + mt * 16 + gid;
            int col = bn + wn * 32 + nt * 8 + tg * 2;
            float v0 = acc[mt][nt][0], v1 = acc[mt][nt][1];
            float v2 = acc[mt][nt][2], v3 = acc[mt][nt][3];
            if (mode == 1) {
                float b0 = bias[col], b1 = bias[col + 1];
                v0 = 1.0f / (1.0f + expf(-(v0 + b0)));
                v1 = 1.0f / (1.0f + expf(-(v1 + b1)));
                v2 = 1.0f / (1.0f + expf(-(v2 + b0)));
                v3 = 1.0f / (1.0f + expf(-(v3 + b1)));
            }
            *reinterpret_cast<float2*>(&Out[(size_t)row * N + col])       = make_float2(v0, v1);
            *reinterpret_cast<float2*>(&Out[(size_t)(row + 8) * N + col]) = make_float2(v2, v3);
        }
    }
}

// ---------------- 3) L2-normalize q and k over Dh=128 ----------------------
__global__ void l2norm_kernel(float* __restrict__ q, float* __restrict__ k) {
    int gw   = (blockIdx.x * blockDim.x + threadIdx.x) >> 5;  // row of 128
    int lane = threadIdx.x & 31;
    if (gw >= Bb * Tt * Hh) return;
    size_t base = (size_t)gw * DhD + lane * 4;

    float4 qv = *reinterpret_cast<const float4*>(q + base);
    float ss = qv.x * qv.x + qv.y * qv.y + qv.z * qv.z + qv.w * qv.w;
    #pragma unroll
    for (int o = 16; o; o >>= 1) ss += __shfl_xor_sync(0xffffffffu, ss, o);
    float inv = 1.0f / fmaxf(sqrtf(ss), 1e-12f);
    qv.x *= inv; qv.y *= inv; qv.z *= inv; qv.w *= inv;
    *reinterpret_cast<float4*>(q + base) = qv;

    float4 kv = *reinterpret_cast<const float4*>(k + base);
    float sk = kv.x * kv.x + kv.y * kv.y + kv.z * kv.z + kv.w * kv.w;
    #pragma unroll
    for (int o = 16; o; o >>= 1) sk += __shfl_xor_sync(0xffffffffu, sk, o);
    float invk = 1.0f / fmaxf(sqrtf(sk), 1e-12f);
    kv.x *= invk; kv.y *= invk; kv.z *= invk; kv.w *= invk;
    *reinterpret_cast<float4*>(k + base) = kv;
}

// ---------------- 4) chunked decayed scan ----------------------------------
__global__ void scan_pass1(const float* __restrict__ k, const float* __restrict__ v,
                           const float* __restrict__ gamma) {
    int blk = blockIdx.x;
    int c  = blk % NCHUNK;
    int bh = blk / NCHUNK;
    int h  = bh % Hh;
    int b  = bh / Hh;
    int d  = threadIdx.x;
    float g = gamma[h];
    size_t idx = ((size_t)(b * Tt + c * LCH)) * Cc + h * DhD + d;
    float S = 0.0f;
    #pragma unroll 4
    for (int i = 0; i < LCH; i++) {
        S = fmaf(g, S, k[idx] * v[idx]);
        idx += Cc;
    }
    g_F[((size_t)bh * NCHUNK + c) * DhD + d] = S;
}

__global__ void scan_pass2(const float* __restrict__ gamma) {
    int tid = blockIdx.x * blockDim.x + threadIdx.x;
    if (tid >= Bb * Hh * DhD) return;
    int d  = tid & (DhD - 1);
    int bh = tid >> 7;
    int h  = bh % Hh;
    float g  = gamma[h];
    float gL = powf(g, (float)LCH);     // exact 1.0 for gamma=1 head
    float carry = 0.0f;
    for (int c = 0; c < NCHUNK; c++) {
        size_t o = ((size_t)bh * NCHUNK + c) * DhD + d;
        g_carry[o] = carry;
        carry = fmaf(gL, carry, g_F[o]);
    }
}

// pass3 output is GEMM input -> pre-round to tf32
__global__ void scan_pass3(const float* __restrict__ k, const float* __restrict__ v,
                           const float* __restrict__ q, const float* __restrict__ gate,
                           const float* __restrict__ gamma) {
    int blk = blockIdx.x;
    int c  = blk % NCHUNK;
    int bh = blk / NCHUNK;
    int h  = bh % Hh;
    int b  = bh / Hh;
    int d  = threadIdx.x;
    float g = gamma[h];
    float S = g_carry[((size_t)bh * NCHUNK + c) * DhD + d];
    size_t idx = ((size_t)(b * Tt + c * LCH)) * Cc + h * DhD + d;
    #pragma unroll 4
    for (int i = 0; i < LCH; i++) {
        S = fmaf(g, S, k[idx] * v[idx]);
        g_att[idx] = tf32r(gate[idx] * S * q[idx]);
        idx += Cc;
    }
}

// ---------------- 5) LayerNorm over C=2048 ---------------------------------
__global__ __launch_bounds__(256)
void ln_kernel(const float* __restrict__ y, const float* __restrict__ lw,
               const float* __restrict__ lb, float* __restrict__ out) {
    int row = blockIdx.x;
    int tid = threadIdx.x;
    const float4* yr = reinterpret_cast<const float4*>(y + (size_t)row * Cc);
    float4* orow     = reinterpret_cast<float4*>(out + (size_t)row * Cc);

    float4 v0 = yr[tid];
    float4 v1 = yr[tid + 256];
    float sum = v0.x + v0.y + v0.z + v0.w + v1.x + v1.y + v1.z + v1.w;
    float sq  = v0.x * v0.x + v0.y * v0.y + v0.z * v0.z + v0.w * v0.w
              + v1.x * v1.x + v1.y * v1.y + v1.z * v1.z + v1.w * v1.w;

    #pragma unroll
    for (int o = 16; o; o >>= 1) {
        sum += __shfl_xor_sync(0xffffffffu, sum, o);
        sq  += __shfl_xor_sync(0xffffffffu, sq, o);
    }
    __shared__ float ssum[8], ssq[8];
    __shared__ float s_mu, s_inv;
    int warp = tid >> 5, lane = tid & 31;
    if (lane == 0) { ssum[warp] = sum; ssq[warp] = sq; }
    __syncthreads();
    if (tid == 0) {
        float ts = 0.0f, tq = 0.0f;
        #pragma unroll
        for (int i = 0; i < 8; i++) { ts += ssum[i]; tq += ssq[i]; }
        float mu  = ts / (float)Cc;
        float var = tq / (float)Cc - mu * mu;
        s_mu  = mu;
        s_inv = rsqrtf(var + 1e-5f);
    }
    __syncthreads();
    float mu = s_mu, inv = s_inv;

    const float4 w0 = reinterpret_cast<const float4*>(lw)[tid];
    const float4 w1 = reinterpret_cast<const float4*>(lw)[tid + 256];
    const float4 b0 = reinterpret_cast<const float4*>(lb)[tid];
    const float4 b1 = reinterpret_cast<const float4*>(lb)[tid + 256];

    float4 o0, o1;
    o0.x = (v0.x - mu) * inv * w0.x + b0.x;
    o0.y = (v0.y - mu) * inv * w0.y + b0.y;
    o0.z = (v0.z - mu) * inv * w0.z + b0.z;
    o0.w = (v0.w - mu) * inv * w0.w + b0.w;
    o1.x = (v1.x - mu) * inv * w1.x + b1.x;
    o1.y = (v1.y - mu) * inv * w1.y + b1.y;
    o1.z = (v1.z - mu) * inv * w1.z + b1.z;
    o1.w = (v1.w - mu) * inv * w1.w + b1.w;
    orow[tid]       = o0;
    orow[tid + 256] = o1;
}

// ---------------- host orchestration ---------------------------------------
extern "C" void kernel_launch(void* const* d_in, const int* in_sizes, int n_in,
                              void* d_out, int out_size) {
    (void)in_sizes; (void)n_in; (void)out_size;
    const float* x      = (const float*)d_in[0];
    const float* Wq     = (const float*)d_in[1];
    const float* Wk     = (const float*)d_in[2];
    const float* Wv     = (const float*)d_in[3];
    const float* Wo     = (const float*)d_in[4];
    const float* conv_w = (const float*)d_in[5];
    const float* conv_b = (const float*)d_in[6];
    const float* gate_w = (const float*)d_in[7];
    const float* gate_b = (const float*)d_in[8];
    const float* ln_w   = (const float*)d_in[9];
    const float* ln_b   = (const float*)d_in[10];
    const float* gamma  = (const float*)d_in[11];

    float *p_xconv, *p_q, *p_k, *p_v, *p_gate, *p_att, *p_y;
    float *p_xt, *p_Wqt, *p_Wkt, *p_Wvt, *p_Wot, *p_Wgt;
    cudaGetSymbolAddress((void**)&p_xconv, g_xconv);
    cudaGetSymbolAddress((void**)&p_q, g_q);
    cudaGetSymbolAddress((void**)&p_k, g_k);
    cudaGetSymbolAddress((void**)&p_v, g_v);
    cudaGetSymbolAddress((void**)&p_gate, g_gate);
    cudaGetSymbolAddress((void**)&p_att, g_att);
    cudaGetSymbolAddress((void**)&p_y, g_y);
    cudaGetSymbolAddress((void**)&p_xt, g_xt);
    cudaGetSymbolAddress((void**)&p_Wqt, g_Wqt);
    cudaGetSymbolAddress((void**)&p_Wkt, g_Wkt);
    cudaGetSymbolAddress((void**)&p_Wvt, g_Wvt);
    cudaGetSymbolAddress((void**)&p_Wot, g_Wot);
    cudaGetSymbolAddress((void**)&p_Wgt, g_Wgt);

    // 0) pre-round GEMM operands to tf32 (pure-bandwidth passes)
    const int wElems = Cc * Cc;            // 4.19M
    cvt_tf32_kernel<<<wElems / 1024, 256>>>(Wq, p_Wqt);
    cvt_tf32_kernel<<<wElems / 1024, 256>>>(Wk, p_Wkt);
    cvt_tf32_kernel<<<wElems / 1024, 256>>>(Wv, p_Wvt);
    cvt_tf32_kernel<<<wElems / 1024, 256>>>(Wo, p_Wot);
    cvt_tf32_kernel<<<wElems / 1024, 256>>>(gate_w, p_Wgt);
    cvt_tf32_kernel<<<(Mrows * Cc) / 1024, 256>>>(x, p_xt);

    // 1) depthwise conv + SiLU (tf32-rounded output)
    conv_silu_kernel<<<(Mrows * Cc) / 256, 256>>>(x, conv_w, conv_b);

    // 2) projections (TF32 tensor cores, cp.async pipelined)
    dim3 ggrid(Cc / 128, Mrows / 128);   // (16, 128)
    gemm_tf32_pipe<<<ggrid, 256>>>(p_xt,    p_Wqt, p_q,    Mrows, Cc, Cc, nullptr, 0);
    gemm_tf32_pipe<<<ggrid, 256>>>(p_xt,    p_Wkt, p_k,    Mrows, Cc, Cc, nullptr, 0);
    gemm_tf32_pipe<<<ggrid, 256>>>(p_xt,    p_Wvt, p_v,    Mrows, Cc, Cc, nullptr, 0);
    gemm_tf32_pipe<<<ggrid, 256>>>(p_xconv, p_Wgt, p_gate, Mrows, Cc, Cc, gate_b, 1);

    // 3) l2norm q, k
    l2norm_kernel<<<(Bb * Tt * Hh) / 8, 256>>>(p_q, p_k);

    // 4) decayed scan (chunked, exact)
    scan_pass1<<<Bb * Hh * NCHUNK, DhD>>>(p_k, p_v, gamma);
    scan_pass2<<<(Bb * Hh * DhD + 127) / 128, 128>>>(gamma);
    scan_pass3<<<Bb * Hh * NCHUNK, DhD>>>(p_k, p_v, p_q, p_gate, gamma);

    // 5) output projection + LayerNorm
    gemm_tf32_pipe<<<ggrid, 256>>>(p_att, p_Wot, p_y, Mrows, Cc, Cc, nullptr, 0);
    ln_kernel<<<Mrows, 256>>>(p_y, ln_w, ln_b, (float*)d_out);
}